// round 16
// baseline (speedup 1.0000x reference)
#include <cuda_runtime.h>
#include <cuda_fp16.h>
#include <math.h>

// Problem constants
#define B_   32
#define T_   128
#define H_   768
#define IN_  256
#define H2_  1536

// exp(-1/20)
#define ALPHA_   0.951229424500714f
#define OMA_     0.048770575499286f
#define DTR_     0.951229424500714f
#define OMD_     0.048770575499286f
#define ETA_     0.1f
#define CIKV_    0.02f

// Output offsets (floats): mem | keys | vals
#define OUT_MEM_   0
#define OUT_KEYS_  18874368
#define OUT_VALS_  22020096

// fp16 scratch
__device__ __half g_ivh[B_ * T_ * H_];          // iv projection, fp16
__device__ __half g_Aparth[6 * B_ * T_ * T_];   // K-split A partials, fp16

// fp16 operand arrays (all single-rounded)
__device__ __half g_xh[B_ * T_ * IN_];
__device__ __half g_Wh[H2_ * IN_];
__device__ __half g_keyh[B_ * T_ * H_];
__device__ __half g_ktrh[B_ * T_ * H_];
__device__ __half g_vtrh[B_ * T_ * H_];
__device__ __half g_Ah[B_ * T_ * T_];           // summed A, fp16

__device__ __forceinline__ float tanh_fast(float x) {
    float y;
    asm("tanh.approx.f32 %0, %1;" : "=f"(y) : "f"(x));
    return y;
}

// ---------------------------------------------------------------------------
// mma.sync helpers (fp16, f32 accum)
// ---------------------------------------------------------------------------
__device__ __forceinline__ void ldsm_x4(unsigned addr, unsigned& r0, unsigned& r1,
                                        unsigned& r2, unsigned& r3) {
    asm volatile("ldmatrix.sync.aligned.m8n8.x4.shared.b16 {%0,%1,%2,%3}, [%4];"
                 : "=r"(r0), "=r"(r1), "=r"(r2), "=r"(r3) : "r"(addr));
}
__device__ __forceinline__ void ldsm_x4t(unsigned addr, unsigned& r0, unsigned& r1,
                                         unsigned& r2, unsigned& r3) {
    asm volatile("ldmatrix.sync.aligned.m8n8.x4.trans.shared.b16 {%0,%1,%2,%3}, [%4];"
                 : "=r"(r0), "=r"(r1), "=r"(r2), "=r"(r3) : "r"(addr));
}
__device__ __forceinline__ void mma16816(float* c, unsigned a0, unsigned a1,
                                         unsigned a2, unsigned a3,
                                         unsigned b0, unsigned b1) {
    asm volatile(
        "mma.sync.aligned.m16n8k16.row.col.f32.f16.f16.f32 "
        "{%0,%1,%2,%3}, {%4,%5,%6,%7}, {%8,%9}, {%0,%1,%2,%3};"
        : "+f"(c[0]), "+f"(c[1]), "+f"(c[2]), "+f"(c[3])
        : "r"(a0), "r"(a1), "r"(a2), "r"(a3), "r"(b0), "r"(b1));
}

// cp.async helpers
__device__ __forceinline__ void cp16(unsigned dst, const void* src) {
    asm volatile("cp.async.cg.shared.global [%0], [%1], 16;" :: "r"(dst), "l"(src));
}
#define CP_COMMIT() asm volatile("cp.async.commit_group;")
#define CP_WAIT0()  asm volatile("cp.async.wait_group 0;" ::: "memory")
#define CP_WAIT1()  asm volatile("cp.async.wait_group 1;" ::: "memory")

#define SRM 40    // smem stride (halves) row-major tiles (128 rows x 32 k)
#define SKM 136   // smem stride (halves) k-major tiles (32 k x 128 m)
#define RM_BUF_HALVES (128 * SRM)            // 5120
#define RM_BUF_BYTES  (RM_BUF_HALVES * 2)    // 10240
#define RM_STAGE_BYTES (2 * RM_BUF_BYTES)
#define KM_BUF_HALVES (32 * SKM)             // 4352
#define KM_BUF_BYTES  (KM_BUF_HALVES * 2)    // 8704
#define KM_STAGE_BYTES (2 * KM_BUF_BYTES)

// Copy one row-major 128x32 fp16 tile into smem via cp.async.
__device__ __forceinline__ void cpa_rm1(unsigned dst, const __half* src,
                                        int ld, int tid)
{
#pragma unroll
    for (int l = 0; l < 2; l++) {
        int c = tid + l * 256;
        int row = c >> 2;
        int q   = c & 3;
        cp16(dst + (unsigned)(row * SRM * 2 + q * 16),
             (const char*)src + (size_t)row * ld * 2 + q * 16);
    }
}
// Copy one k-major 32x128 fp16 tile into smem.
__device__ __forceinline__ void cpa_km1(unsigned dst, const __half* src,
                                        int ld, int tid)
{
#pragma unroll
    for (int l = 0; l < 2; l++) {
        int c = tid + l * 256;
        int row = c >> 4;
        int q   = c & 15;
        cp16(dst + (unsigned)(row * SKM * 2 + q * 16),
             (const char*)src + (size_t)row * ld * 2 + q * 16);
    }
}

// BK=32 compute step, row-major tiles, single pass (K1/K3).
__device__ __forceinline__ void mma_step_rm1(
    unsigned bAh, unsigned bBh,
    int wm, int wn, int lane, float acc[4][4][4])
{
    const int lr = lane & 15;
    const int kh = (lane >> 4) * 8;
#pragma unroll
    for (int ks = 0; ks < 32; ks += 16) {
        unsigned ah[4][4], bh[4][2];
#pragma unroll
        for (int i = 0; i < 4; i++) {
            unsigned off = 2u * ((wm * 64 + i * 16 + lr) * SRM + ks + kh);
            ldsm_x4(bAh + off, ah[i][0], ah[i][1], ah[i][2], ah[i][3]);
        }
#pragma unroll
        for (int p = 0; p < 2; p++) {
            unsigned off = 2u * ((wn * 32 + p * 16 + lr) * SRM + ks + kh);
            unsigned r0, r1, r2, r3;
            ldsm_x4(bBh + off, r0, r1, r2, r3);
            bh[p * 2 + 0][0] = r0; bh[p * 2 + 0][1] = r2;
            bh[p * 2 + 1][0] = r1; bh[p * 2 + 1][1] = r3;
        }
#pragma unroll
        for (int i = 0; i < 4; i++)
#pragma unroll
            for (int j = 0; j < 4; j++)
                mma16816(acc[i][j], ah[i][0], ah[i][1], ah[i][2], ah[i][3],
                         bh[j][0], bh[j][1]);
    }
}

// BK=32 compute step, k-major tiles, single pass (K5).
__device__ __forceinline__ void mma_step_km1(
    unsigned bAh, unsigned bBh,
    int wm, int wn, int lane, float acc[4][4][4])
{
    const int krow = (lane & 7) + ((lane >> 4) << 3);
    const int mcol = ((lane >> 3) & 1) * 8;
#pragma unroll
    for (int ks = 0; ks < 32; ks += 16) {
        unsigned ah[4][4], bh[4][2];
#pragma unroll
        for (int i = 0; i < 4; i++) {
            unsigned off = 2u * ((ks + krow) * SKM + wm * 64 + i * 16 + mcol);
            ldsm_x4t(bAh + off, ah[i][0], ah[i][1], ah[i][2], ah[i][3]);
        }
#pragma unroll
        for (int p = 0; p < 2; p++) {
            unsigned off = 2u * ((ks + krow) * SKM + wn * 32 + p * 16 + mcol);
            unsigned r0, r1, r2, r3;
            ldsm_x4t(bBh + off, r0, r1, r2, r3);
            bh[p * 2 + 0][0] = r0; bh[p * 2 + 0][1] = r2;
            bh[p * 2 + 1][0] = r1; bh[p * 2 + 1][1] = r3;
        }
#pragma unroll
        for (int i = 0; i < 4; i++)
#pragma unroll
            for (int j = 0; j < 4; j++)
                mma16816(acc[i][j], ah[i][0], ah[i][1], ah[i][2], ah[i][3],
                         bh[j][0], bh[j][1]);
    }
}

// Epilogue: write 4x4 m16n8 tiles to gmem (f32), scaled.
__device__ __forceinline__ void epilogue(float* dst, int ldc, float scale,
                                         int wm, int wn, int lane,
                                         float acc[4][4][4])
{
    const int r0 = lane >> 2;
    const int c0 = (lane & 3) * 2;
#pragma unroll
    for (int i = 0; i < 4; i++)
#pragma unroll
        for (int j = 0; j < 4; j++) {
            int row = wm * 64 + i * 16 + r0;
            int col = wn * 32 + j * 8 + c0;
            float2 v0 = make_float2(scale * acc[i][j][0], scale * acc[i][j][1]);
            float2 v1 = make_float2(scale * acc[i][j][2], scale * acc[i][j][3]);
            *(float2*)&dst[row * ldc + col] = v0;
            *(float2*)&dst[(row + 8) * ldc + col] = v1;
        }
}

// Epilogue variant: write fp16 (__half2 pairs).
__device__ __forceinline__ void epilogue_h(__half* dst, int ldc,
                                           int wm, int wn, int lane,
                                           float acc[4][4][4])
{
    const int r0 = lane >> 2;
    const int c0 = (lane & 3) * 2;
#pragma unroll
    for (int i = 0; i < 4; i++)
#pragma unroll
        for (int j = 0; j < 4; j++) {
            int row = wm * 64 + i * 16 + r0;
            int col = wn * 32 + j * 8 + c0;
            *(__half2*)&dst[row * ldc + col] =
                __floats2half2_rn(acc[i][j][0], acc[i][j][1]);
            *(__half2*)&dst[(row + 8) * ldc + col] =
                __floats2half2_rn(acc[i][j][2], acc[i][j][3]);
        }
}

// ---------------------------------------------------------------------------
// K0: round x and W to fp16
// ---------------------------------------------------------------------------
#define XN_ (B_ * T_ * IN_)   // 1048576
#define WN_ (H2_ * IN_)       // 393216

__global__ __launch_bounds__(256) void k0_convert(
    const float* __restrict__ x, const float* __restrict__ W)
{
    int i4 = (blockIdx.x * 256 + threadIdx.x) * 4;
    if (i4 < XN_) {
        float4 v = *(const float4*)&x[i4];
        g_xh[i4 + 0] = __float2half_rn(v.x);
        g_xh[i4 + 1] = __float2half_rn(v.y);
        g_xh[i4 + 2] = __float2half_rn(v.z);
        g_xh[i4 + 3] = __float2half_rn(v.w);
    } else if (i4 < XN_ + WN_) {
        int off = i4 - XN_;
        float4 v = *(const float4*)&W[off];
        g_Wh[off + 0] = __float2half_rn(v.x);
        g_Wh[off + 1] = __float2half_rn(v.y);
        g_Wh[off + 2] = __float2half_rn(v.z);
        g_Wh[off + 3] = __float2half_rn(v.w);
    }
}

// ---------------------------------------------------------------------------
// K1: i = x@W^T (M=4096 N=1536 K=256, NK=8), 3-stage cp.async pipeline.
//     ik tiles (bx<6): fused key scan (bit-identical f32 arithmetic).
//     iv tiles (bx>=6): fp16 epilogue into g_ivh. Dyn smem 67584B.
// ---------------------------------------------------------------------------
#define SC1 132

__global__ __launch_bounds__(256, 2) void k1_gemm_in(float* __restrict__ out)
{
    extern __shared__ __half dyn[];
    const int m0 = blockIdx.y * 128;
    const int n0 = blockIdx.x * 128;
    const int tid = threadIdx.x;
    const int warp = tid >> 5, lane = tid & 31;
    const int wm = warp >> 2, wn = warp & 3;

    unsigned sb = (unsigned)__cvta_generic_to_shared(dyn);

    float acc[4][4][4];
#pragma unroll
    for (int i = 0; i < 4; i++)
#pragma unroll
        for (int j = 0; j < 4; j++)
#pragma unroll
            for (int r = 0; r < 4; r++) acc[i][j][r] = 0.f;

    const __half* Ah = &g_xh[(size_t)m0 * IN_];
    const __half* Bh = &g_Wh[(size_t)n0 * IN_];

#define NK1 8
    cpa_rm1(sb,                 Ah, IN_, tid);
    cpa_rm1(sb + RM_BUF_BYTES,  Bh, IN_, tid);
    CP_COMMIT();
    cpa_rm1(sb + RM_STAGE_BYTES,                Ah + 32, IN_, tid);
    cpa_rm1(sb + RM_STAGE_BYTES + RM_BUF_BYTES, Bh + 32, IN_, tid);
    CP_COMMIT();

    for (int k = 0; k < NK1; k++) {
        if (k + 1 < NK1) CP_WAIT1(); else CP_WAIT0();
        __syncthreads();
        if (k + 2 < NK1) {
            unsigned s2 = sb + (unsigned)(((k + 2) % 3) * RM_STAGE_BYTES);
            cpa_rm1(s2,                Ah + (k + 2) * 32, IN_, tid);
            cpa_rm1(s2 + RM_BUF_BYTES, Bh + (k + 2) * 32, IN_, tid);
            CP_COMMIT();
        }
        unsigned s = sb + (unsigned)((k % 3) * RM_STAGE_BYTES);
        mma_step_rm1(s, s + RM_BUF_BYTES, wm, wn, lane, acc);
    }

    if (blockIdx.x >= 6) {
        // iv half: fp16 epilogue into g_ivh [b*T][H]
        epilogue_h(&g_ivh[(size_t)m0 * H_ + (n0 - H_)], H_, wm, wn, lane, acc);
        return;
    }

    // ik half: stage tile in smem (aliases stage buffers; GEMM complete)
    __syncthreads();
    float* sc = (float*)dyn;  // [128][SC1]
    {
        const int r0 = lane >> 2;
        const int c0 = (lane & 3) * 2;
#pragma unroll
        for (int i = 0; i < 4; i++)
#pragma unroll
            for (int j = 0; j < 4; j++) {
                int row = wm * 64 + i * 16 + r0;
                int col = wn * 32 + j * 8 + c0;
                sc[row * SC1 + col]           = acc[i][j][0];
                sc[row * SC1 + col + 1]       = acc[i][j][1];
                sc[(row + 8) * SC1 + col]     = acc[i][j][2];
                sc[(row + 8) * SC1 + col + 1] = acc[i][j][3];
            }
    }
    __syncthreads();

    if (tid < 128) {
        const int b = blockIdx.y;
        const int h = n0 + tid;
        const int base = (b * T_) * H_ + h;
        float* keyso = &out[OUT_KEYS_ + base];

        float kv = 0.f, ktr = 0.f;
#pragma unroll 4
        for (int t = 0; t < T_; t++) {
            kv = ALPHA_ * kv + OMA_ * sc[t * SC1 + tid];
            float key = tanh_fast(kv);
            ktr = DTR_ * ktr + OMD_ * key;
            keyso[t * H_] = key;
            g_keyh[base + t * H_] = __float2half_rn(key);
            g_ktrh[base + t * H_] = __float2half_rn(ktr);
        }
    }
}

// ---------------------------------------------------------------------------
// K3: fp16 A partials.  grid (6,32). NK=4. 3-stage pipeline.
// ---------------------------------------------------------------------------
__global__ __launch_bounds__(256, 2) void k3_gemm_A()
{
    extern __shared__ __half dyn[];
    const int p = blockIdx.x;
    const int b = blockIdx.y;
    const int tid = threadIdx.x;
    const int warp = tid >> 5, lane = tid & 31;
    const int wm = warp >> 2, wn = warp & 3;

    unsigned sb = (unsigned)__cvta_generic_to_shared(dyn);

    const size_t base = (size_t)b * T_ * H_ + p * 128;
    const __half* Ah = &g_keyh[base];
    const __half* Bh = &g_ktrh[base];

    float acc[4][4][4];
#pragma unroll
    for (int i = 0; i < 4; i++)
#pragma unroll
        for (int j = 0; j < 4; j++)
#pragma unroll
            for (int r = 0; r < 4; r++) acc[i][j][r] = 0.f;

#define NK3 4
    cpa_rm1(sb,                Ah, H_, tid);
    cpa_rm1(sb + RM_BUF_BYTES, Bh, H_, tid);
    CP_COMMIT();
    cpa_rm1(sb + RM_STAGE_BYTES,                Ah + 32, H_, tid);
    cpa_rm1(sb + RM_STAGE_BYTES + RM_BUF_BYTES, Bh + 32, H_, tid);
    CP_COMMIT();

    for (int k = 0; k < NK3; k++) {
        if (k + 1 < NK3) CP_WAIT1(); else CP_WAIT0();
        __syncthreads();
        if (k + 2 < NK3) {
            unsigned s2 = sb + (unsigned)(((k + 2) % 3) * RM_STAGE_BYTES);
            cpa_rm1(s2,                Ah + (k + 2) * 32, H_, tid);
            cpa_rm1(s2 + RM_BUF_BYTES, Bh + (k + 2) * 32, H_, tid);
            CP_COMMIT();
        }
        unsigned s = sb + (unsigned)((k % 3) * RM_STAGE_BYTES);
        mma_step_rm1(s, s + RM_BUF_BYTES, wm, wn, lane, acc);
    }
    epilogue_h(&g_Aparth[(size_t)(p * B_ + b) * (T_ * T_)], T_, wm, wn, lane, acc);
}

// ---------------------------------------------------------------------------
// K35: sum the 6 fp16 partials (f32 accumulate), write fp16 g_Ah.
//      8 elems/thread. grid 256 x 256.
// ---------------------------------------------------------------------------
__global__ __launch_bounds__(256) void k35_sum_A()
{
    int e = (blockIdx.x * 256 + threadIdx.x) * 8;   // < 524288
    float s[8];
#pragma unroll
    for (int i = 0; i < 8; i++) s[i] = 0.f;
#pragma unroll
    for (int p = 0; p < 6; p++) {
        uint4 u = *(const uint4*)&g_Aparth[(size_t)p * B_ * T_ * T_ + e];
        const __half2* hp = (const __half2*)&u;
#pragma unroll
        for (int q = 0; q < 4; q++) {
            float2 f = __half22float2(hp[q]);
            s[q * 2 + 0] += f.x;
            s[q * 2 + 1] += f.y;
        }
    }
    __half h[8];
#pragma unroll
    for (int i = 0; i < 8; i++) h[i] = __float2half_rn(s[i]);
    *(uint4*)&g_Ah[e] = *(const uint4*)h;
}

// ---------------------------------------------------------------------------
// K4: value-side scan with tensor-core cross phase. iv now read as fp16.
// ---------------------------------------------------------------------------
#define SA4 136   // A_s16 stride (halves)
#define SV4 264   // vtr16 stride (halves)
#define SP4 260   // p_s stride (floats)
#define K4_SMEM (128 * SA4 * 2 + 128 * SV4 * 2 + 16 * SP4 * 4)

__global__ __launch_bounds__(256) void k4_scan_val(float* __restrict__ out)
{
    extern __shared__ char sm4raw[];
    __half* A_s16 = (__half*)sm4raw;                              // [128][SA4]
    __half* vtr16 = (__half*)(sm4raw + 128 * SA4 * 2);            // [128][SV4]
    float*  p_s   = (float*)(sm4raw + 128 * SA4 * 2 + 128 * SV4 * 2); // [16][SP4]

    const int b    = blockIdx.x / 3;
    const int hb   = blockIdx.x % 3;
    const int tid  = threadIdx.x;
    const int warp = tid >> 5;
    const int lane = tid & 31;
    const int h    = hb * 256 + tid;

    unsigned aA = (unsigned)__cvta_generic_to_shared(A_s16);
    unsigned aV = (unsigned)__cvta_generic_to_shared(vtr16);

    // Load summed fp16 A tile (32KB) via cp.async into padded smem rows.
    {
        const char* src = (const char*)&g_Ah[(size_t)b * (T_ * T_)];
#pragma unroll
        for (int l = 0; l < 8; l++) {
            int c = tid + l * 256;
            int row = c >> 4, q = c & 15;
            cp16(aA + (unsigned)(row * SA4 * 2 + q * 16), src + (size_t)c * 16);
        }
        CP_COMMIT();
        CP_WAIT0();
    }
    __syncthreads();

    const __half* ivp = &g_ivh[(size_t)(b * T_) * H_ + h];
    const int gbase = (b * T_) * H_ + h;
    float* valso = &out[OUT_VALS_ + gbase];

    const int lr   = lane & 15;
    const int kh   = (lane >> 4) * 8;
    const int krow = (lane & 7) + ((lane >> 4) << 3);
    const int mcol = ((lane >> 3) & 1) * 8;
    const int r0w  = lane >> 2;
    const int c0w  = (lane & 3) * 2;

    float vv = 0.f, vtr = 0.f;

    for (int t0 = 0; t0 < T_; t0 += 16) {
        float iv_blk[16];
#pragma unroll
        for (int j = 0; j < 16; j++)
            iv_blk[j] = __half2float(ivp[(t0 + j) * H_]);

        if (t0 > 0) {
            float c[4][4];
#pragma unroll
            for (int j = 0; j < 4; j++)
#pragma unroll
                for (int r = 0; r < 4; r++) c[j][r] = 0.f;

            for (int ks = 0; ks < t0; ks += 16) {
                unsigned af0, af1, af2, af3;
                ldsm_x4(aA + 2u * ((t0 + lr) * SA4 + ks + kh), af0, af1, af2, af3);
                unsigned bf[4][2];
#pragma unroll
                for (int p = 0; p < 2; p++) {
                    unsigned r0, r1, r2, r3;
                    ldsm_x4t(aV + 2u * ((ks + krow) * SV4 + warp * 32 + p * 16 + mcol),
                             r0, r1, r2, r3);
                    bf[p * 2 + 0][0] = r0; bf[p * 2 + 0][1] = r2;
                    bf[p * 2 + 1][0] = r1; bf[p * 2 + 1][1] = r3;
                }
#pragma unroll
                for (int j = 0; j < 4; j++)
                    mma16816(c[j], af0, af1, af2, af3, bf[j][0], bf[j][1]);
            }
#pragma unroll
            for (int j = 0; j < 4; j++) {
                int col = warp * 32 + j * 8 + c0w;
                p_s[r0w * SP4 + col]           = c[j][0];
                p_s[r0w * SP4 + col + 1]       = c[j][1];
                p_s[(r0w + 8) * SP4 + col]     = c[j][2];
                p_s[(r0w + 8) * SP4 + col + 1] = c[j][3];
            }
        }
        __syncthreads();

        float vtr_blk[16];
#pragma unroll
        for (int j = 0; j < 16; j++) {
            const int t = t0 + j;
            float a = (t0 > 0) ? p_s[j * SP4 + tid] : 0.f;
#pragma unroll
            for (int sj = 0; sj < j; sj++)
                a = fmaf(__half2float(A_s16[t * SA4 + t0 + sj]), vtr_blk[sj], a);
            float ikv = CIKV_ * a;

            vv = ALPHA_ * vv + OMA_ * (iv_blk[j] + ikv);
            float val = tanh_fast(vv);
            vtr = DTR_ * vtr + OMD_ * val;
            vtr_blk[j] = vtr;

            valso[t * H_] = val;
            __half v16 = __float2half_rn(vtr);
            vtr16[t * SV4 + tid] = v16;
            g_vtrh[gbase + t * H_] = v16;
        }
        __syncthreads();
    }
}

// ---------------------------------------------------------------------------
// K5: mem[b][i][j] = eta * sum_s vtr[b,s,i]*ktr[b,s,j]
//     k-major fp16 single-pass, trans-ldmatrix, 3-stage pipeline.
// ---------------------------------------------------------------------------
__global__ __launch_bounds__(256, 2) void k5_gemm_mem(float* __restrict__ out)
{
    extern __shared__ __half dyn[];
    const int b  = blockIdx.z;
    const int i0 = blockIdx.y * 128;
    const int j0 = blockIdx.x * 128;
    const int tid = threadIdx.x;
    const int warp = tid >> 5, lane = tid & 31;
    const int wm = warp >> 2, wn = warp & 3;

    unsigned sb = (unsigned)__cvta_generic_to_shared(dyn);

    const size_t bb = (size_t)b * T_ * H_;
    const __half* Ah = &g_vtrh[bb + i0];
    const __half* Bh = &g_ktrh[bb + j0];

    float acc[4][4][4];
#pragma unroll
    for (int i = 0; i < 4; i++)
#pragma unroll
        for (int j = 0; j < 4; j++)
#pragma unroll
            for (int r = 0; r < 4; r++) acc[i][j][r] = 0.f;

#define NK5 4
    cpa_km1(sb,                Ah, H_, tid);
    cpa_km1(sb + KM_BUF_BYTES, Bh, H_, tid);
    CP_COMMIT();
    cpa_km1(sb + KM_STAGE_BYTES,                Ah + (size_t)32 * H_, H_, tid);
    cpa_km1(sb + KM_STAGE_BYTES + KM_BUF_BYTES, Bh + (size_t)32 * H_, H_, tid);
    CP_COMMIT();

    for (int k = 0; k < NK5; k++) {
        if (k + 1 < NK5) CP_WAIT1(); else CP_WAIT0();
        __syncthreads();
        if (k + 2 < NK5) {
            unsigned s2 = sb + (unsigned)(((k + 2) % 3) * KM_STAGE_BYTES);
            const size_t so = (size_t)(k + 2) * 32 * H_;
            cpa_km1(s2,                Ah + so, H_, tid);
            cpa_km1(s2 + KM_BUF_BYTES, Bh + so, H_, tid);
            CP_COMMIT();
        }
        unsigned s = sb + (unsigned)((k % 3) * KM_STAGE_BYTES);
        mma_step_km1(s, s + KM_BUF_BYTES, wm, wn, lane, acc);
    }
    epilogue(&out[(size_t)b * (H_ * H_) + (size_t)i0 * H_ + j0], H_, ETA_,
             wm, wn, lane, acc);
}

// ---------------------------------------------------------------------------
extern "C" void kernel_launch(void* const* d_in, const int* in_sizes, int n_in,
                              void* d_out, int out_size)
{
    const float* x = (const float*)d_in[0];   // (32,128,256)
    const float* W = (const float*)d_in[1];   // (1536,256)
    float* out = (float*)d_out;               // mem | keys | vals

    const int smem_k1 = 128 * SC1 * 4;            // 67584 (>= 3*RM_STAGE_BYTES)
    const int smem_k3 = 3 * RM_STAGE_BYTES;       // 61440
    const int smem_k5 = 3 * KM_STAGE_BYTES;       // 52224

    (void)cudaFuncSetAttribute(k1_gemm_in,
        cudaFuncAttributeMaxDynamicSharedMemorySize, smem_k1);
    (void)cudaFuncSetAttribute(k3_gemm_A,
        cudaFuncAttributeMaxDynamicSharedMemorySize, smem_k3);
    (void)cudaFuncSetAttribute(k5_gemm_mem,
        cudaFuncAttributeMaxDynamicSharedMemorySize, smem_k5);
    (void)cudaFuncSetAttribute(k4_scan_val,
        cudaFuncAttributeMaxDynamicSharedMemorySize, K4_SMEM);

    k0_convert<<<(XN_ + WN_ + 1023) / 1024, 256>>>(x, W);
    k1_gemm_in<<<dim3(12, 32), 256, smem_k1>>>(out);
    k3_gemm_A<<<dim3(6, 32), 256, smem_k3>>>();
    k35_sum_A<<<256, 256>>>();
    k4_scan_val<<<96, 256, K4_SMEM>>>(out);
    k5_gemm_mem<<<dim3(6, 6, 32), 256, smem_k5>>>(out);
}

// round 17
// speedup vs baseline: 1.0447x; 1.0447x over previous
#include <cuda_runtime.h>
#include <cuda_fp16.h>
#include <math.h>

// Problem constants
#define B_   32
#define T_   128
#define H_   768
#define IN_  256
#define H2_  1536

// exp(-1/20)
#define ALPHA_   0.951229424500714f
#define OMA_     0.048770575499286f
#define DTR_     0.951229424500714f
#define OMD_     0.048770575499286f
#define ETA_     0.1f
#define CIKV_    0.02f

// Output offsets (floats): mem | keys | vals
#define OUT_MEM_   0
#define OUT_KEYS_  18874368
#define OUT_VALS_  22020096

// Scratch
__device__ float  g_i[B_ * T_ * H2_];           // only iv half is written/read (f32)
__device__ __half g_Aparth[6 * B_ * T_ * T_];   // K-split A partials, fp16

// fp16 operand arrays (all single-rounded)
__device__ __half g_xh[B_ * T_ * IN_];
__device__ __half g_Wh[H2_ * IN_];
__device__ __half g_keyh[B_ * T_ * H_];
__device__ __half g_ktrh[B_ * T_ * H_];
__device__ __half g_vtrh[B_ * T_ * H_];
__device__ __half g_Ah[B_ * T_ * T_];           // summed A, fp16

__device__ __forceinline__ float tanh_fast(float x) {
    float y;
    asm("tanh.approx.f32 %0, %1;" : "=f"(y) : "f"(x));
    return y;
}

// ---------------------------------------------------------------------------
// mma.sync helpers (fp16, f32 accum)
// ---------------------------------------------------------------------------
__device__ __forceinline__ void ldsm_x4(unsigned addr, unsigned& r0, unsigned& r1,
                                        unsigned& r2, unsigned& r3) {
    asm volatile("ldmatrix.sync.aligned.m8n8.x4.shared.b16 {%0,%1,%2,%3}, [%4];"
                 : "=r"(r0), "=r"(r1), "=r"(r2), "=r"(r3) : "r"(addr));
}
__device__ __forceinline__ void ldsm_x4t(unsigned addr, unsigned& r0, unsigned& r1,
                                         unsigned& r2, unsigned& r3) {
    asm volatile("ldmatrix.sync.aligned.m8n8.x4.trans.shared.b16 {%0,%1,%2,%3}, [%4];"
                 : "=r"(r0), "=r"(r1), "=r"(r2), "=r"(r3) : "r"(addr));
}
__device__ __forceinline__ void mma16816(float* c, unsigned a0, unsigned a1,
                                         unsigned a2, unsigned a3,
                                         unsigned b0, unsigned b1) {
    asm volatile(
        "mma.sync.aligned.m16n8k16.row.col.f32.f16.f16.f32 "
        "{%0,%1,%2,%3}, {%4,%5,%6,%7}, {%8,%9}, {%0,%1,%2,%3};"
        : "+f"(c[0]), "+f"(c[1]), "+f"(c[2]), "+f"(c[3])
        : "r"(a0), "r"(a1), "r"(a2), "r"(a3), "r"(b0), "r"(b1));
}

// cp.async helpers
__device__ __forceinline__ void cp16(unsigned dst, const void* src) {
    asm volatile("cp.async.cg.shared.global [%0], [%1], 16;" :: "r"(dst), "l"(src));
}
#define CP_COMMIT() asm volatile("cp.async.commit_group;")
#define CP_WAIT0()  asm volatile("cp.async.wait_group 0;" ::: "memory")
#define CP_WAIT1()  asm volatile("cp.async.wait_group 1;" ::: "memory")

// streaming f32x2 store (for K5's write-once output)
__device__ __forceinline__ void stg_cs_f2(float* p, float a, float b) {
    asm volatile("st.global.cs.v2.f32 [%0], {%1, %2};"
                 :: "l"(p), "f"(a), "f"(b) : "memory");
}

#define SRM 40    // smem stride (halves) row-major tiles (128 rows x 32 k)
#define SKM 136   // smem stride (halves) k-major tiles (32 k x 128 m)
#define RM_BUF_HALVES (128 * SRM)            // 5120
#define RM_BUF_BYTES  (RM_BUF_HALVES * 2)    // 10240
#define RM_STAGE_BYTES (2 * RM_BUF_BYTES)
#define KM_BUF_HALVES (32 * SKM)             // 4352
#define KM_BUF_BYTES  (KM_BUF_HALVES * 2)    // 8704
#define KM_STAGE_BYTES (2 * KM_BUF_BYTES)

// Copy one row-major 128x32 fp16 tile into smem via cp.async.
__device__ __forceinline__ void cpa_rm1(unsigned dst, const __half* src,
                                        int ld, int tid)
{
#pragma unroll
    for (int l = 0; l < 2; l++) {
        int c = tid + l * 256;
        int row = c >> 2;
        int q   = c & 3;
        cp16(dst + (unsigned)(row * SRM * 2 + q * 16),
             (const char*)src + (size_t)row * ld * 2 + q * 16);
    }
}
// Copy one k-major 32x128 fp16 tile into smem.
__device__ __forceinline__ void cpa_km1(unsigned dst, const __half* src,
                                        int ld, int tid)
{
#pragma unroll
    for (int l = 0; l < 2; l++) {
        int c = tid + l * 256;
        int row = c >> 4;
        int q   = c & 15;
        cp16(dst + (unsigned)(row * SKM * 2 + q * 16),
             (const char*)src + (size_t)row * ld * 2 + q * 16);
    }
}

// BK=32 compute step, row-major tiles, single pass (K1/K3).
__device__ __forceinline__ void mma_step_rm1(
    unsigned bAh, unsigned bBh,
    int wm, int wn, int lane, float acc[4][4][4])
{
    const int lr = lane & 15;
    const int kh = (lane >> 4) * 8;
#pragma unroll
    for (int ks = 0; ks < 32; ks += 16) {
        unsigned ah[4][4], bh[4][2];
#pragma unroll
        for (int i = 0; i < 4; i++) {
            unsigned off = 2u * ((wm * 64 + i * 16 + lr) * SRM + ks + kh);
            ldsm_x4(bAh + off, ah[i][0], ah[i][1], ah[i][2], ah[i][3]);
        }
#pragma unroll
        for (int p = 0; p < 2; p++) {
            unsigned off = 2u * ((wn * 32 + p * 16 + lr) * SRM + ks + kh);
            unsigned r0, r1, r2, r3;
            ldsm_x4(bBh + off, r0, r1, r2, r3);
            bh[p * 2 + 0][0] = r0; bh[p * 2 + 0][1] = r2;
            bh[p * 2 + 1][0] = r1; bh[p * 2 + 1][1] = r3;
        }
#pragma unroll
        for (int i = 0; i < 4; i++)
#pragma unroll
            for (int j = 0; j < 4; j++)
                mma16816(acc[i][j], ah[i][0], ah[i][1], ah[i][2], ah[i][3],
                         bh[j][0], bh[j][1]);
    }
}

// BK=32 compute step, k-major tiles, single pass (K5).
__device__ __forceinline__ void mma_step_km1(
    unsigned bAh, unsigned bBh,
    int wm, int wn, int lane, float acc[4][4][4])
{
    const int krow = (lane & 7) + ((lane >> 4) << 3);
    const int mcol = ((lane >> 3) & 1) * 8;
#pragma unroll
    for (int ks = 0; ks < 32; ks += 16) {
        unsigned ah[4][4], bh[4][2];
#pragma unroll
        for (int i = 0; i < 4; i++) {
            unsigned off = 2u * ((ks + krow) * SKM + wm * 64 + i * 16 + mcol);
            ldsm_x4t(bAh + off, ah[i][0], ah[i][1], ah[i][2], ah[i][3]);
        }
#pragma unroll
        for (int p = 0; p < 2; p++) {
            unsigned off = 2u * ((ks + krow) * SKM + wn * 32 + p * 16 + mcol);
            unsigned r0, r1, r2, r3;
            ldsm_x4t(bBh + off, r0, r1, r2, r3);
            bh[p * 2 + 0][0] = r0; bh[p * 2 + 0][1] = r2;
            bh[p * 2 + 1][0] = r1; bh[p * 2 + 1][1] = r3;
        }
#pragma unroll
        for (int i = 0; i < 4; i++)
#pragma unroll
            for (int j = 0; j < 4; j++)
                mma16816(acc[i][j], ah[i][0], ah[i][1], ah[i][2], ah[i][3],
                         bh[j][0], bh[j][1]);
    }
}

// Epilogue: write 4x4 m16n8 tiles to gmem (f32), scaled.
__device__ __forceinline__ void epilogue(float* dst, int ldc, float scale,
                                         int wm, int wn, int lane,
                                         float acc[4][4][4])
{
    const int r0 = lane >> 2;
    const int c0 = (lane & 3) * 2;
#pragma unroll
    for (int i = 0; i < 4; i++)
#pragma unroll
        for (int j = 0; j < 4; j++) {
            int row = wm * 64 + i * 16 + r0;
            int col = wn * 32 + j * 8 + c0;
            float2 v0 = make_float2(scale * acc[i][j][0], scale * acc[i][j][1]);
            float2 v1 = make_float2(scale * acc[i][j][2], scale * acc[i][j][3]);
            *(float2*)&dst[row * ldc + col] = v0;
            *(float2*)&dst[(row + 8) * ldc + col] = v1;
        }
}

// Epilogue variant: streaming stores (K5 mem output, write-once).
__device__ __forceinline__ void epilogue_cs(float* dst, int ldc, float scale,
                                            int wm, int wn, int lane,
                                            float acc[4][4][4])
{
    const int r0 = lane >> 2;
    const int c0 = (lane & 3) * 2;
#pragma unroll
    for (int i = 0; i < 4; i++)
#pragma unroll
        for (int j = 0; j < 4; j++) {
            int row = wm * 64 + i * 16 + r0;
            int col = wn * 32 + j * 8 + c0;
            stg_cs_f2(&dst[row * ldc + col],
                      scale * acc[i][j][0], scale * acc[i][j][1]);
            stg_cs_f2(&dst[(row + 8) * ldc + col],
                      scale * acc[i][j][2], scale * acc[i][j][3]);
        }
}

// Epilogue variant: write fp16 (__half2 pairs) — K3 partials.
__device__ __forceinline__ void epilogue_h(__half* dst, int ldc,
                                           int wm, int wn, int lane,
                                           float acc[4][4][4])
{
    const int r0 = lane >> 2;
    const int c0 = (lane & 3) * 2;
#pragma unroll
    for (int i = 0; i < 4; i++)
#pragma unroll
        for (int j = 0; j < 4; j++) {
            int row = wm * 64 + i * 16 + r0;
            int col = wn * 32 + j * 8 + c0;
            *(__half2*)&dst[row * ldc + col] =
                __floats2half2_rn(acc[i][j][0], acc[i][j][1]);
            *(__half2*)&dst[(row + 8) * ldc + col] =
                __floats2half2_rn(acc[i][j][2], acc[i][j][3]);
        }
}

// ---------------------------------------------------------------------------
// K0: round x and W to fp16
// ---------------------------------------------------------------------------
#define XN_ (B_ * T_ * IN_)   // 1048576
#define WN_ (H2_ * IN_)       // 393216

__global__ __launch_bounds__(256) void k0_convert(
    const float* __restrict__ x, const float* __restrict__ W)
{
    int i4 = (blockIdx.x * 256 + threadIdx.x) * 4;
    if (i4 < XN_) {
        float4 v = *(const float4*)&x[i4];
        g_xh[i4 + 0] = __float2half_rn(v.x);
        g_xh[i4 + 1] = __float2half_rn(v.y);
        g_xh[i4 + 2] = __float2half_rn(v.z);
        g_xh[i4 + 3] = __float2half_rn(v.w);
    } else if (i4 < XN_ + WN_) {
        int off = i4 - XN_;
        float4 v = *(const float4*)&W[off];
        g_Wh[off + 0] = __float2half_rn(v.x);
        g_Wh[off + 1] = __float2half_rn(v.y);
        g_Wh[off + 2] = __float2half_rn(v.z);
        g_Wh[off + 3] = __float2half_rn(v.w);
    }
}

// ---------------------------------------------------------------------------
// K1: i = x@W^T (M=4096 N=1536 K=256, NK=8), 3-stage cp.async pipeline.
//     ik tiles (bx<6): fused key scan (bit-identical f32 arithmetic).
//     iv tiles (bx>=6): f32 epilogue into g_i (proven R14 path).
// ---------------------------------------------------------------------------
#define SC1 132

__global__ __launch_bounds__(256, 2) void k1_gemm_in(float* __restrict__ out)
{
    extern __shared__ __half dyn[];
    const int m0 = blockIdx.y * 128;
    const int n0 = blockIdx.x * 128;
    const int tid = threadIdx.x;
    const int warp = tid >> 5, lane = tid & 31;
    const int wm = warp >> 2, wn = warp & 3;

    unsigned sb = (unsigned)__cvta_generic_to_shared(dyn);

    float acc[4][4][4];
#pragma unroll
    for (int i = 0; i < 4; i++)
#pragma unroll
        for (int j = 0; j < 4; j++)
#pragma unroll
            for (int r = 0; r < 4; r++) acc[i][j][r] = 0.f;

    const __half* Ah = &g_xh[(size_t)m0 * IN_];
    const __half* Bh = &g_Wh[(size_t)n0 * IN_];

#define NK1 8
    cpa_rm1(sb,                 Ah, IN_, tid);
    cpa_rm1(sb + RM_BUF_BYTES,  Bh, IN_, tid);
    CP_COMMIT();
    cpa_rm1(sb + RM_STAGE_BYTES,                Ah + 32, IN_, tid);
    cpa_rm1(sb + RM_STAGE_BYTES + RM_BUF_BYTES, Bh + 32, IN_, tid);
    CP_COMMIT();

    for (int k = 0; k < NK1; k++) {
        if (k + 1 < NK1) CP_WAIT1(); else CP_WAIT0();
        __syncthreads();
        if (k + 2 < NK1) {
            unsigned s2 = sb + (unsigned)(((k + 2) % 3) * RM_STAGE_BYTES);
            cpa_rm1(s2,                Ah + (k + 2) * 32, IN_, tid);
            cpa_rm1(s2 + RM_BUF_BYTES, Bh + (k + 2) * 32, IN_, tid);
            CP_COMMIT();
        }
        unsigned s = sb + (unsigned)((k % 3) * RM_STAGE_BYTES);
        mma_step_rm1(s, s + RM_BUF_BYTES, wm, wn, lane, acc);
    }

    if (blockIdx.x >= 6) {
        epilogue(&g_i[(size_t)m0 * H2_ + n0], H2_, 1.f, wm, wn, lane, acc);
        return;
    }

    // ik half: stage tile in smem (aliases stage buffers; GEMM complete)
    __syncthreads();
    float* sc = (float*)dyn;  // [128][SC1]
    {
        const int r0 = lane >> 2;
        const int c0 = (lane & 3) * 2;
#pragma unroll
        for (int i = 0; i < 4; i++)
#pragma unroll
            for (int j = 0; j < 4; j++) {
                int row = wm * 64 + i * 16 + r0;
                int col = wn * 32 + j * 8 + c0;
                sc[row * SC1 + col]           = acc[i][j][0];
                sc[row * SC1 + col + 1]       = acc[i][j][1];
                sc[(row + 8) * SC1 + col]     = acc[i][j][2];
                sc[(row + 8) * SC1 + col + 1] = acc[i][j][3];
            }
    }
    __syncthreads();

    if (tid < 128) {
        const int b = blockIdx.y;
        const int h = n0 + tid;
        const int base = (b * T_) * H_ + h;
        float* keyso = &out[OUT_KEYS_ + base];

        float kv = 0.f, ktr = 0.f;
#pragma unroll 4
        for (int t = 0; t < T_; t++) {
            kv = ALPHA_ * kv + OMA_ * sc[t * SC1 + tid];
            float key = tanh_fast(kv);
            ktr = DTR_ * ktr + OMD_ * key;
            keyso[t * H_] = key;
            g_keyh[base + t * H_] = __float2half_rn(key);
            g_ktrh[base + t * H_] = __float2half_rn(ktr);
        }
    }
}

// ---------------------------------------------------------------------------
// K3: fp16 A partials. grid (6,32). NK=4. 3-stage pipeline.
// ---------------------------------------------------------------------------
__global__ __launch_bounds__(256, 2) void k3_gemm_A()
{
    extern __shared__ __half dyn[];
    const int p = blockIdx.x;
    const int b = blockIdx.y;
    const int tid = threadIdx.x;
    const int warp = tid >> 5, lane = tid & 31;
    const int wm = warp >> 2, wn = warp & 3;

    unsigned sb = (unsigned)__cvta_generic_to_shared(dyn);

    const size_t base = (size_t)b * T_ * H_ + p * 128;
    const __half* Ah = &g_keyh[base];
    const __half* Bh = &g_ktrh[base];

    float acc[4][4][4];
#pragma unroll
    for (int i = 0; i < 4; i++)
#pragma unroll
        for (int j = 0; j < 4; j++)
#pragma unroll
            for (int r = 0; r < 4; r++) acc[i][j][r] = 0.f;

#define NK3 4
    cpa_rm1(sb,                Ah, H_, tid);
    cpa_rm1(sb + RM_BUF_BYTES, Bh, H_, tid);
    CP_COMMIT();
    cpa_rm1(sb + RM_STAGE_BYTES,                Ah + 32, H_, tid);
    cpa_rm1(sb + RM_STAGE_BYTES + RM_BUF_BYTES, Bh + 32, H_, tid);
    CP_COMMIT();

    for (int k = 0; k < NK3; k++) {
        if (k + 1 < NK3) CP_WAIT1(); else CP_WAIT0();
        __syncthreads();
        if (k + 2 < NK3) {
            unsigned s2 = sb + (unsigned)(((k + 2) % 3) * RM_STAGE_BYTES);
            cpa_rm1(s2,                Ah + (k + 2) * 32, H_, tid);
            cpa_rm1(s2 + RM_BUF_BYTES, Bh + (k + 2) * 32, H_, tid);
            CP_COMMIT();
        }
        unsigned s = sb + (unsigned)((k % 3) * RM_STAGE_BYTES);
        mma_step_rm1(s, s + RM_BUF_BYTES, wm, wn, lane, acc);
    }
    epilogue_h(&g_Aparth[(size_t)(p * B_ + b) * (T_ * T_)], T_, wm, wn, lane, acc);
}

// ---------------------------------------------------------------------------
// K35: sum the 6 fp16 partials (f32 accumulate), write fp16 g_Ah.
//      8 elems/thread. grid 256 x 256.
// ---------------------------------------------------------------------------
__global__ __launch_bounds__(256) void k35_sum_A()
{
    int e = (blockIdx.x * 256 + threadIdx.x) * 8;   // < 524288
    float s[8];
#pragma unroll
    for (int i = 0; i < 8; i++) s[i] = 0.f;
#pragma unroll
    for (int p = 0; p < 6; p++) {
        uint4 u = *(const uint4*)&g_Aparth[(size_t)p * B_ * T_ * T_ + e];
        const __half2* hp = (const __half2*)&u;
#pragma unroll
        for (int q = 0; q < 4; q++) {
            float2 f = __half22float2(hp[q]);
            s[q * 2 + 0] += f.x;
            s[q * 2 + 1] += f.y;
        }
    }
    __half h[8];
#pragma unroll
    for (int i = 0; i < 8; i++) h[i] = __float2half_rn(s[i]);
    *(uint4*)&g_Ah[e] = *(const uint4*)h;
}

// ---------------------------------------------------------------------------
// K4: value-side scan with tensor-core cross phase (proven core).
//     iv read from f32 g_i (R14 path).
// ---------------------------------------------------------------------------
#define SA4 136   // A_s16 stride (halves)
#define SV4 264   // vtr16 stride (halves)
#define SP4 260   // p_s stride (floats)
#define K4_SMEM (128 * SA4 * 2 + 128 * SV4 * 2 + 16 * SP4 * 4)

__global__ __launch_bounds__(256) void k4_scan_val(float* __restrict__ out)
{
    extern __shared__ char sm4raw[];
    __half* A_s16 = (__half*)sm4raw;                              // [128][SA4]
    __half* vtr16 = (__half*)(sm4raw + 128 * SA4 * 2);            // [128][SV4]
    float*  p_s   = (float*)(sm4raw + 128 * SA4 * 2 + 128 * SV4 * 2); // [16][SP4]

    const int b    = blockIdx.x / 3;
    const int hb   = blockIdx.x % 3;
    const int tid  = threadIdx.x;
    const int warp = tid >> 5;
    const int lane = tid & 31;
    const int h    = hb * 256 + tid;

    unsigned aA = (unsigned)__cvta_generic_to_shared(A_s16);
    unsigned aV = (unsigned)__cvta_generic_to_shared(vtr16);

    // Load summed fp16 A tile (32KB) via cp.async into padded smem rows.
    {
        const char* src = (const char*)&g_Ah[(size_t)b * (T_ * T_)];
#pragma unroll
        for (int l = 0; l < 8; l++) {
            int c = tid + l * 256;
            int row = c >> 4, q = c & 15;
            cp16(aA + (unsigned)(row * SA4 * 2 + q * 16), src + (size_t)c * 16);
        }
        CP_COMMIT();
        CP_WAIT0();
    }
    __syncthreads();

    const float* ivp = &g_i[b * T_ * H2_ + H_ + h];
    const int gbase = (b * T_) * H_ + h;
    float* valso = &out[OUT_VALS_ + gbase];

    const int lr   = lane & 15;
    const int kh   = (lane >> 4) * 8;
    const int krow = (lane & 7) + ((lane >> 4) << 3);
    const int mcol = ((lane >> 3) & 1) * 8;
    const int r0w  = lane >> 2;
    const int c0w  = (lane & 3) * 2;

    float vv = 0.f, vtr = 0.f;

    for (int t0 = 0; t0 < T_; t0 += 16) {
        float iv_blk[16];
#pragma unroll
        for (int j = 0; j < 16; j++) iv_blk[j] = ivp[(t0 + j) * H2_];

        if (t0 > 0) {
            float c[4][4];
#pragma unroll
            for (int j = 0; j < 4; j++)
#pragma unroll
                for (int r = 0; r < 4; r++) c[j][r] = 0.f;

            for (int ks = 0; ks < t0; ks += 16) {
                unsigned af0, af1, af2, af3;
                ldsm_x4(aA + 2u * ((t0 + lr) * SA4 + ks + kh), af0, af1, af2, af3);
                unsigned bf[4][2];
#pragma unroll
                for (int p = 0; p < 2; p++) {
                    unsigned r0, r1, r2, r3;
                    ldsm_x4t(aV + 2u * ((ks + krow) * SV4 + warp * 32 + p * 16 + mcol),
                             r0, r1, r2, r3);
                    bf[p * 2 + 0][0] = r0; bf[p * 2 + 0][1] = r2;
                    bf[p * 2 + 1][0] = r1; bf[p * 2 + 1][1] = r3;
                }
#pragma unroll
                for (int j = 0; j < 4; j++)
                    mma16816(c[j], af0, af1, af2, af3, bf[j][0], bf[j][1]);
            }
#pragma unroll
            for (int j = 0; j < 4; j++) {
                int col = warp * 32 + j * 8 + c0w;
                p_s[r0w * SP4 + col]           = c[j][0];
                p_s[r0w * SP4 + col + 1]       = c[j][1];
                p_s[(r0w + 8) * SP4 + col]     = c[j][2];
                p_s[(r0w + 8) * SP4 + col + 1] = c[j][3];
            }
        }
        __syncthreads();

        float vtr_blk[16];
#pragma unroll
        for (int j = 0; j < 16; j++) {
            const int t = t0 + j;
            float a = (t0 > 0) ? p_s[j * SP4 + tid] : 0.f;
#pragma unroll
            for (int sj = 0; sj < j; sj++)
                a = fmaf(__half2float(A_s16[t * SA4 + t0 + sj]), vtr_blk[sj], a);
            float ikv = CIKV_ * a;

            vv = ALPHA_ * vv + OMA_ * (iv_blk[j] + ikv);
            float val = tanh_fast(vv);
            vtr = DTR_ * vtr + OMD_ * val;
            vtr_blk[j] = vtr;

            valso[t * H_] = val;
            __half v16 = __float2half_rn(vtr);
            vtr16[t * SV4 + tid] = v16;
            g_vtrh[gbase + t * H_] = v16;
        }
        __syncthreads();
    }
}

// ---------------------------------------------------------------------------
// K5: mem[b][i][j] = eta * sum_s vtr[b,s,i]*ktr[b,s,j]
//     k-major fp16 single-pass, trans-ldmatrix, 3-stage pipeline,
//     streaming (.cs) epilogue. grid (6,6,32), NK=4.
// ---------------------------------------------------------------------------
__global__ __launch_bounds__(256, 2) void k5_gemm_mem(float* __restrict__ out)
{
    extern __shared__ __half dyn[];
    const int b  = blockIdx.z;
    const int i0 = blockIdx.y * 128;
    const int j0 = blockIdx.x * 128;
    const int tid = threadIdx.x;
    const int warp = tid >> 5, lane = tid & 31;
    const int wm = warp >> 2, wn = warp & 3;

    unsigned sb = (unsigned)__cvta_generic_to_shared(dyn);

    const size_t bb = (size_t)b * T_ * H_;
    const __half* Ah = &g_vtrh[bb + i0];
    const __half* Bh = &g_ktrh[bb + j0];

    float acc[4][4][4];
#pragma unroll
    for (int i = 0; i < 4; i++)
#pragma unroll
        for (int j = 0; j < 4; j++)
#pragma unroll
            for (int r = 0; r < 4; r++) acc[i][j][r] = 0.f;

#define NK5 4
    cpa_km1(sb,                Ah, H_, tid);
    cpa_km1(sb + KM_BUF_BYTES, Bh, H_, tid);
    CP_COMMIT();
    cpa_km1(sb + KM_STAGE_BYTES,                Ah + (size_t)32 * H_, H_, tid);
    cpa_km1(sb + KM_STAGE_BYTES + KM_BUF_BYTES, Bh + (size_t)32 * H_, H_, tid);
    CP_COMMIT();

    for (int k = 0; k < NK5; k++) {
        if (k + 1 < NK5) CP_WAIT1(); else CP_WAIT0();
        __syncthreads();
        if (k + 2 < NK5) {
            unsigned s2 = sb + (unsigned)(((k + 2) % 3) * KM_STAGE_BYTES);
            const size_t so = (size_t)(k + 2) * 32 * H_;
            cpa_km1(s2,                Ah + so, H_, tid);
            cpa_km1(s2 + KM_BUF_BYTES, Bh + so, H_, tid);
            CP_COMMIT();
        }
        unsigned s = sb + (unsigned)((k % 3) * KM_STAGE_BYTES);
        mma_step_km1(s, s + KM_BUF_BYTES, wm, wn, lane, acc);
    }
    epilogue_cs(&out[(size_t)b * (H_ * H_) + (size_t)i0 * H_ + j0], H_, ETA_,
                wm, wn, lane, acc);
}

// ---------------------------------------------------------------------------
extern "C" void kernel_launch(void* const* d_in, const int* in_sizes, int n_in,
                              void* d_out, int out_size)
{
    const float* x = (const float*)d_in[0];   // (32,128,256)
    const float* W = (const float*)d_in[1];   // (1536,256)
    float* out = (float*)d_out;               // mem | keys | vals

    const int smem_k1 = 128 * SC1 * 4;            // 67584 (>= 3*RM_STAGE_BYTES)
    const int smem_k3 = 3 * RM_STAGE_BYTES;       // 61440
    const int smem_k5 = 3 * KM_STAGE_BYTES;       // 52224

    (void)cudaFuncSetAttribute(k1_gemm_in,
        cudaFuncAttributeMaxDynamicSharedMemorySize, smem_k1);
    (void)cudaFuncSetAttribute(k3_gemm_A,
        cudaFuncAttributeMaxDynamicSharedMemorySize, smem_k3);
    (void)cudaFuncSetAttribute(k5_gemm_mem,
        cudaFuncAttributeMaxDynamicSharedMemorySize, smem_k5);
    (void)cudaFuncSetAttribute(k4_scan_val,
        cudaFuncAttributeMaxDynamicSharedMemorySize, K4_SMEM);

    k0_convert<<<(XN_ + WN_ + 1023) / 1024, 256>>>(x, W);
    k1_gemm_in<<<dim3(12, 32), 256, smem_k1>>>(out);
    k3_gemm_A<<<dim3(6, 32), 256, smem_k3>>>();
    k35_sum_A<<<256, 256>>>();
    k4_scan_val<<<96, 256, K4_SMEM>>>(out);
    k5_gemm_mem<<<dim3(6, 6, 32), 256, smem_k5>>>(out);
}